// round 16
// baseline (speedup 1.0000x reference)
#include <cuda_runtime.h>
#include <cuda_fp16.h>
#include <cstdint>

#define NF 128          // node feature dim F
#define EFD 7           // edge feature dim
#define NMAX 100000     // node count

// Scratch for h = nfeat @ W.T + b, stored fp16 (25.6 MB)
__device__ __half g_h[(size_t)NMAX * NF];
// Pre-split W (fp16 hi/lo), row-major 128x128
__device__ __half g_Whi[128 * 128];
__device__ __half g_Wlo[128 * 128];

__device__ __forceinline__ uint32_t smem_u32(const void* p) {
    uint32_t a;
    asm("{ .reg .u64 t; cvta.to.shared.u64 t, %1; cvt.u32.u64 %0, t; }"
        : "=r"(a) : "l"(p));
    return a;
}

// ===========================================================================
// Kernel 0: split W into fp16 hi/lo once (16384 elements).
// ===========================================================================
__global__ void __launch_bounds__(256)
split_w_kernel(const float* __restrict__ W)
{
    int i = (blockIdx.x * 256 + threadIdx.x) * 4;
    float4 v = *reinterpret_cast<const float4*>(W + i);
    __half2 h01 = __floats2half2_rn(v.x, v.y);
    __half2 h23 = __floats2half2_rn(v.z, v.w);
    __half2 l01 = __floats2half2_rn(v.x - __low2float(h01), v.y - __high2float(h01));
    __half2 l23 = __floats2half2_rn(v.z - __low2float(h23), v.w - __high2float(h23));
    uint2 hs, ls;
    hs.x = *reinterpret_cast<uint32_t*>(&h01);
    hs.y = *reinterpret_cast<uint32_t*>(&h23);
    ls.x = *reinterpret_cast<uint32_t*>(&l01);
    ls.y = *reinterpret_cast<uint32_t*>(&l23);
    *reinterpret_cast<uint2*>(g_Whi + i) = hs;
    *reinterpret_cast<uint2*>(g_Wlo + i) = ls;
}

// ===========================================================================
// Kernel A: PERSISTENT fp16 hi/lo split mma.sync GEMM (3 passes, fp32 accum)
// 296 CTAs (2/SM); each grid-strides over tiles with W resident in smem.
// ===========================================================================
#define PITCH_W 136
#define PITCH_A 72
#define SWH 0
#define SWL (128 * PITCH_W)
#define SAH (2 * 128 * PITCH_W)
#define SAL (SAH + 128 * PITCH_A)
#define GEMM_SMEM_HALVES (SAL + 128 * PITCH_A)
#define GEMM_SMEM_BYTES (GEMM_SMEM_HALVES * 2)

__device__ __forceinline__ void ldm_x4(uint32_t* r, uint32_t addr) {
    asm volatile("ldmatrix.sync.aligned.m8n8.x4.shared.b16 {%0,%1,%2,%3}, [%4];"
                 : "=r"(r[0]), "=r"(r[1]), "=r"(r[2]), "=r"(r[3]) : "r"(addr));
}
__device__ __forceinline__ void ldm_x2(uint32_t* r, uint32_t addr) {
    asm volatile("ldmatrix.sync.aligned.m8n8.x2.shared.b16 {%0,%1}, [%2];"
                 : "=r"(r[0]), "=r"(r[1]) : "r"(addr));
}
__device__ __forceinline__ void mma_f16(float* d, const uint32_t* a, const uint32_t* b) {
    asm volatile(
        "mma.sync.aligned.m16n8k16.row.col.f32.f16.f16.f32 "
        "{%0,%1,%2,%3}, {%4,%5,%6,%7}, {%8,%9}, {%0,%1,%2,%3};"
        : "+f"(d[0]), "+f"(d[1]), "+f"(d[2]), "+f"(d[3])
        : "r"(a[0]), "r"(a[1]), "r"(a[2]), "r"(a[3]), "r"(b[0]), "r"(b[1]));
}

__device__ __forceinline__ void split_store4(__half* base_h, __half* base_l,
                                             uint32_t off, float4 v) {
    __half2 h01 = __floats2half2_rn(v.x, v.y);
    __half2 h23 = __floats2half2_rn(v.z, v.w);
    float lx = v.x - __low2float(h01);
    float ly = v.y - __high2float(h01);
    float lz = v.z - __low2float(h23);
    float lw = v.w - __high2float(h23);
    __half2 l01 = __floats2half2_rn(lx, ly);
    __half2 l23 = __floats2half2_rn(lz, lw);
    uint2 hs, ls;
    hs.x = *reinterpret_cast<uint32_t*>(&h01);
    hs.y = *reinterpret_cast<uint32_t*>(&h23);
    ls.x = *reinterpret_cast<uint32_t*>(&l01);
    ls.y = *reinterpret_cast<uint32_t*>(&l23);
    *reinterpret_cast<uint2*>(base_h + off) = hs;
    *reinterpret_cast<uint2*>(base_l + off) = ls;
}

__global__ void __launch_bounds__(256, 2)
gemm_h_mma(const float* __restrict__ A,
           const __half* __restrict__ Whi,
           const __half* __restrict__ Wlo,
           const float* __restrict__ bvec,
           const float* __restrict__ root,
           const float* __restrict__ degs,
           __half* __restrict__ hout,
           float* __restrict__ out,
           int N, int ntiles)
{
    extern __shared__ __half smh[];

    const int tid  = threadIdx.x;
    const int wid  = tid >> 5;
    const int lane = tid & 31;
    const int g    = lane >> 2;
    const int tg   = lane & 3;

    const int m_base = (wid & 1) * 64;
    const int n_base = (wid >> 1) * 32;

    // ---- copy pre-split W into padded smem once per CTA ----
#pragma unroll
    for (int it = 0; it < 8; it++) {
        int idx = it * 256 + tid;
        int r = idx >> 4, c8 = (idx & 15) * 8;
        uint4 vh = *reinterpret_cast<const uint4*>(Whi + r * 128 + c8);
        uint4 vl = *reinterpret_cast<const uint4*>(Wlo + r * 128 + c8);
        *reinterpret_cast<uint4*>(smh + SWH + r * PITCH_W + c8) = vh;
        *reinterpret_cast<uint4*>(smh + SWL + r * PITCH_W + c8) = vl;
    }

    const uint32_t sb = smem_u32(smh);
    const int aRow = lane & 15;
    const int aK   = (lane >> 4) * 8;
    const uint32_t aH0 = sb + (uint32_t)(SAH + (m_base + aRow) * PITCH_A + aK) * 2;
    const uint32_t aL0 = sb + (uint32_t)(SAL + (m_base + aRow) * PITCH_A + aK) * 2;
    const int bRow = lane & 7;
    const int bK   = ((lane >> 3) & 1) * 8;
    const uint32_t bH0 = sb + (uint32_t)(SWH + (n_base + bRow) * PITCH_W + bK) * 2;
    const uint32_t bL0 = sb + (uint32_t)(SWL + (n_base + bRow) * PITCH_W + bK) * 2;

    for (int t = blockIdx.x; t < ntiles; t += gridDim.x) {
        const int m0 = t * 128;

        float acc[4][4][4];
#pragma unroll
        for (int mt = 0; mt < 4; mt++)
#pragma unroll
            for (int nt = 0; nt < 4; nt++)
#pragma unroll
                for (int q = 0; q < 4; q++) acc[mt][nt][q] = 0.f;

        for (int kh = 0; kh < 2; kh++) {
            __syncthreads();    // protects A smem (prev kh / prev tile) + W (1st iter)
#pragma unroll
            for (int it = 0; it < 8; it++) {
                int idx = it * 256 + tid;
                int r = idx >> 4, c4 = (idx & 15) * 4;
                int gm = m0 + r;
                float4 v = make_float4(0.f, 0.f, 0.f, 0.f);
                if (gm < N)
                    v = *reinterpret_cast<const float4*>(A + (size_t)gm * NF + kh * 64 + c4);
                split_store4(smh + SAH, smh + SAL, (uint32_t)(r * PITCH_A + c4), v);
            }
            __syncthreads();

#pragma unroll
            for (int ks = 0; ks < 4; ks++) {
                const uint32_t koA = (uint32_t)(ks * 16 * 2);
                const uint32_t koB = (uint32_t)((kh * 64 + ks * 16) * 2);
                uint32_t ah[4][4], al[4][4], bh[4][2], bl[4][2];
#pragma unroll
                for (int mt = 0; mt < 4; mt++) {
                    ldm_x4(ah[mt], aH0 + (uint32_t)(mt * 16 * PITCH_A * 2) + koA);
                    ldm_x4(al[mt], aL0 + (uint32_t)(mt * 16 * PITCH_A * 2) + koA);
                }
#pragma unroll
                for (int nt = 0; nt < 4; nt++) {
                    ldm_x2(bh[nt], bH0 + (uint32_t)(nt * 8 * PITCH_W * 2) + koB);
                    ldm_x2(bl[nt], bL0 + (uint32_t)(nt * 8 * PITCH_W * 2) + koB);
                }
#pragma unroll
                for (int mt = 0; mt < 4; mt++)
#pragma unroll
                    for (int nt = 0; nt < 4; nt++) {
                        mma_f16(acc[mt][nt], ah[mt], bh[nt]);
                        mma_f16(acc[mt][nt], ah[mt], bl[nt]);
                        mma_f16(acc[mt][nt], al[mt], bh[nt]);
                    }
            }
        }

        // ---- epilogue (registers + gmem only; no smem) ----
#pragma unroll
        for (int nt = 0; nt < 4; nt++) {
            const int c = n_base + nt * 8 + 2 * tg;
            const float b0 = __ldg(bvec + c),  b1 = __ldg(bvec + c + 1);
            const float r0 = __ldg(root + c),  r1 = __ldg(root + c + 1);
#pragma unroll
            for (int mt = 0; mt < 4; mt++) {
                const int ra = m0 + m_base + mt * 16 + g;
                const int rb = ra + 8;
                if (ra < N) {
                    float invd = 1.0f / __ldg(degs + ra);
                    float h0 = acc[mt][nt][0] + b0;
                    float h1 = acc[mt][nt][1] + b1;
                    float2 ov = make_float2(fmaxf(h0 + r0, 0.f) * invd,
                                            fmaxf(h1 + r1, 0.f) * invd);
                    __half2 hp = __floats2half2_rn(h0, h1);
                    *reinterpret_cast<uint32_t*>(hout + (size_t)ra * NF + c) =
                        *reinterpret_cast<uint32_t*>(&hp);
                    *reinterpret_cast<float2*>(out + (size_t)ra * NF + c) = ov;
                }
                if (rb < N) {
                    float invd = 1.0f / __ldg(degs + rb);
                    float h0 = acc[mt][nt][2] + b0;
                    float h1 = acc[mt][nt][3] + b1;
                    float2 ov = make_float2(fmaxf(h0 + r0, 0.f) * invd,
                                            fmaxf(h1 + r1, 0.f) * invd);
                    __half2 hp = __floats2half2_rn(h0, h1);
                    *reinterpret_cast<uint32_t*>(hout + (size_t)rb * NF + c) =
                        *reinterpret_cast<uint32_t*>(&hp);
                    *reinterpret_cast<float2*>(out + (size_t)rb * NF + c) = ov;
                }
            }
        }
    }
}

// ===========================================================================
// Kernel B (R13 design, best measured 158.4us): 8 edges/warp/iter,
// fp16 gathers, next-iter src prefetch, efeat in two 28-float chunks.
// ===========================================================================
__global__ void __launch_bounds__(256, 2)
edge_kernel(const float* __restrict__ efeat,   // [E,7]
            const float* __restrict__ norm,    // [E]
            const int*   __restrict__ src,
            const int*   __restrict__ dst,
            const float* __restrict__ We,      // [128,7]
            const float* __restrict__ be,      // [128]
            const __half* __restrict__ h,      // [N,128] fp16
            float* __restrict__ out,           // [N,128]
            int E)
{
    const int lane = threadIdx.x & 31;
    const int j0   = lane * 4;

    float w[4][EFD], bias[4];
#pragma unroll
    for (int j = 0; j < 4; j++) {
        bias[j] = __ldg(be + j0 + j);
#pragma unroll
        for (int k = 0; k < EFD; k++)
            w[j][k] = __ldg(We + (size_t)(j0 + j) * EFD + k);
    }

    const int warp_id = (blockIdx.x * blockDim.x + threadIdx.x) >> 5;
    const int nwarps  = (gridDim.x * blockDim.x) >> 5;
    const int Emain   = E & ~7;
    const int estep   = nwarps * 8;

    int e0 = warp_id * 8;
    int4 sa, sb;
    if (e0 < Emain) {
        sa = __ldcs(reinterpret_cast<const int4*>(src + e0));
        sb = __ldcs(reinterpret_cast<const int4*>(src + e0 + 4));
    }

    for (; e0 < Emain; e0 += estep) {
        const int s[8] = {sa.x, sa.y, sa.z, sa.w, sb.x, sb.y, sb.z, sb.w};
        uint2 hvr[8];
#pragma unroll
        for (int u = 0; u < 8; u++)
            hvr[u] = *reinterpret_cast<const uint2*>(h + (size_t)s[u] * NF + j0);

        const int e1 = e0 + estep;
        if (e1 < Emain) {
            sa = __ldcs(reinterpret_cast<const int4*>(src + e1));
            sb = __ldcs(reinterpret_cast<const int4*>(src + e1 + 4));
        }

        const int4   da = __ldcs(reinterpret_cast<const int4*>(dst + e0));
        const int4   db = __ldcs(reinterpret_cast<const int4*>(dst + e0 + 4));
        const float4 na = __ldcs(reinterpret_cast<const float4*>(norm + e0));
        const float4 nb = __ldcs(reinterpret_cast<const float4*>(norm + e0 + 4));

        const int   d[8]  = {da.x, da.y, da.z, da.w, db.x, db.y, db.z, db.w};
        const float nr[8] = {na.x, na.y, na.z, na.w, nb.x, nb.y, nb.z, nb.w};

#pragma unroll
        for (int cch = 0; cch < 2; cch++) {
            float ef[28];
#pragma unroll
            for (int q = 0; q < 7; q++)
                *reinterpret_cast<float4*>(&ef[q * 4]) =
                    __ldcs(reinterpret_cast<const float4*>(
                        efeat + (size_t)(e0 + cch * 4) * EFD + q * 4));

#pragma unroll
            for (int uu = 0; uu < 4; uu++) {
                const int u = cch * 4 + uu;
                float v0 = bias[0], v1 = bias[1], v2 = bias[2], v3 = bias[3];
#pragma unroll
                for (int k = 0; k < EFD; k++) {
                    float x = ef[uu * EFD + k];
                    v0 = fmaf(w[0][k], x, v0);
                    v1 = fmaf(w[1][k], x, v1);
                    v2 = fmaf(w[2][k], x, v2);
                    v3 = fmaf(w[3][k], x, v3);
                }
                __half2 p0 = *reinterpret_cast<__half2*>(&hvr[u].x);
                __half2 p1 = *reinterpret_cast<__half2*>(&hvr[u].y);
                float2 f01 = __half22float2(p0);
                float2 f23 = __half22float2(p1);

                v0 = fmaxf(f01.x + v0, 0.f) * nr[u];
                v1 = fmaxf(f01.y + v1, 0.f) * nr[u];
                v2 = fmaxf(f23.x + v2, 0.f) * nr[u];
                v3 = fmaxf(f23.y + v3, 0.f) * nr[u];

                float* p = out + (size_t)d[u] * NF + j0;
                asm volatile("red.global.add.v4.f32 [%0], {%1, %2, %3, %4};"
                             :: "l"(p), "f"(v0), "f"(v1), "f"(v2), "f"(v3)
                             : "memory");
            }
        }
    }

    // tail — warp 0
    if (warp_id == 0) {
        for (int e = Emain; e < E; e++) {
            const int   se = __ldg(src + e);
            const int   de = __ldg(dst + e);
            const float nre = __ldg(norm + e);
            float efs[EFD];
#pragma unroll
            for (int k = 0; k < EFD; k++)
                efs[k] = __ldg(efeat + (size_t)e * EFD + k);
            uint2 hraw = *reinterpret_cast<const uint2*>(h + (size_t)se * NF + j0);
            __half2 p0 = *reinterpret_cast<__half2*>(&hraw.x);
            __half2 p1 = *reinterpret_cast<__half2*>(&hraw.y);
            float2 f01 = __half22float2(p0);
            float2 f23 = __half22float2(p1);
            float v0 = bias[0], v1 = bias[1], v2 = bias[2], v3 = bias[3];
#pragma unroll
            for (int k = 0; k < EFD; k++) {
                v0 = fmaf(w[0][k], efs[k], v0);
                v1 = fmaf(w[1][k], efs[k], v1);
                v2 = fmaf(w[2][k], efs[k], v2);
                v3 = fmaf(w[3][k], efs[k], v3);
            }
            v0 = fmaxf(f01.x + v0, 0.f) * nre;
            v1 = fmaxf(f01.y + v1, 0.f) * nre;
            v2 = fmaxf(f23.x + v2, 0.f) * nre;
            v3 = fmaxf(f23.y + v3, 0.f) * nre;
            float* p = out + (size_t)de * NF + j0;
            asm volatile("red.global.add.v4.f32 [%0], {%1, %2, %3, %4};"
                         :: "l"(p), "f"(v0), "f"(v1), "f"(v2), "f"(v3)
                         : "memory");
        }
    }
}

// ---------------------------------------------------------------------------
// Launch.  Input order: nfeat, efeat, degs, norm, src, dst, W, b, We, be, root
// ---------------------------------------------------------------------------
extern "C" void kernel_launch(void* const* d_in, const int* in_sizes, int n_in,
                              void* d_out, int out_size)
{
    const float* nfeat = (const float*)d_in[0];
    const float* efeat = (const float*)d_in[1];
    const float* degs  = (const float*)d_in[2];
    const float* norm  = (const float*)d_in[3];
    const int*   src   = (const int*)  d_in[4];
    const int*   dst   = (const int*)  d_in[5];
    const float* W     = (const float*)d_in[6];
    const float* b     = (const float*)d_in[7];
    const float* We    = (const float*)d_in[8];
    const float* be    = (const float*)d_in[9];
    const float* root  = (const float*)d_in[10];
    float* out = (float*)d_out;

    const int N = in_sizes[0] / NF;
    const int E = in_sizes[4];

    __half *h, *whi, *wlo;
    cudaGetSymbolAddress((void**)&h,   g_h);
    cudaGetSymbolAddress((void**)&whi, g_Whi);
    cudaGetSymbolAddress((void**)&wlo, g_Wlo);

    cudaFuncSetAttribute(gemm_h_mma, cudaFuncAttributeMaxDynamicSharedMemorySize,
                         GEMM_SMEM_BYTES);

    split_w_kernel<<<16, 256>>>(W);

    const int ntiles = (N + 127) / 128;
    int gridA = ntiles < 296 ? ntiles : 296;
    gemm_h_mma<<<gridA, 256, GEMM_SMEM_BYTES>>>(nfeat, whi, wlo, b, root, degs,
                                                h, out, N, ntiles);

    int gridB = 1480;
    edge_kernel<<<gridB, 256>>>(efeat, norm, src, dst, We, be, h, out, E);
}

// round 17
// speedup vs baseline: 1.0420x; 1.0420x over previous
#include <cuda_runtime.h>
#include <cuda_fp16.h>
#include <cstdint>

#define NF 128          // node feature dim F
#define EFD 7           // edge feature dim
#define NMAX 100000     // node count

// Scratch for h = nfeat @ W.T + b, stored fp16 (25.6 MB)
__device__ __half g_h[(size_t)NMAX * NF];
// Pre-split W (fp16 hi/lo), row-major 128x128
__device__ __half g_Whi[128 * 128];
__device__ __half g_Wlo[128 * 128];

__device__ __forceinline__ uint32_t smem_u32(const void* p) {
    uint32_t a;
    asm("{ .reg .u64 t; cvta.to.shared.u64 t, %1; cvt.u32.u64 %0, t; }"
        : "=r"(a) : "l"(p));
    return a;
}

// ===========================================================================
// Kernel 0: split W into fp16 hi/lo once (16384 elements).
// ===========================================================================
__global__ void __launch_bounds__(256)
split_w_kernel(const float* __restrict__ W)
{
    int i = (blockIdx.x * 256 + threadIdx.x) * 4;
    float4 v = *reinterpret_cast<const float4*>(W + i);
    __half2 h01 = __floats2half2_rn(v.x, v.y);
    __half2 h23 = __floats2half2_rn(v.z, v.w);
    __half2 l01 = __floats2half2_rn(v.x - __low2float(h01), v.y - __high2float(h01));
    __half2 l23 = __floats2half2_rn(v.z - __low2float(h23), v.w - __high2float(h23));
    uint2 hs, ls;
    hs.x = *reinterpret_cast<uint32_t*>(&h01);
    hs.y = *reinterpret_cast<uint32_t*>(&h23);
    ls.x = *reinterpret_cast<uint32_t*>(&l01);
    ls.y = *reinterpret_cast<uint32_t*>(&l23);
    *reinterpret_cast<uint2*>(g_Whi + i) = hs;
    *reinterpret_cast<uint2*>(g_Wlo + i) = ls;
}

// ===========================================================================
// Kernel A: fp16 2-term mma.sync GEMM  D = Ah*(Wh + Wl), fp32 accum.
//   A converted to fp16 hi only (error ~2^-12, well under 1e-3 budget).
// W pre-split in gmem -> prologue pure copy. smem 88KB -> 2 CTAs/SM.
// ===========================================================================
#define PITCH_W 136
#define PITCH_A 72
#define SWH 0
#define SWL (128 * PITCH_W)
#define SAH (2 * 128 * PITCH_W)
#define GEMM_SMEM_HALVES (SAH + 128 * PITCH_A)
#define GEMM_SMEM_BYTES (GEMM_SMEM_HALVES * 2)

__device__ __forceinline__ void ldm_x4(uint32_t* r, uint32_t addr) {
    asm volatile("ldmatrix.sync.aligned.m8n8.x4.shared.b16 {%0,%1,%2,%3}, [%4];"
                 : "=r"(r[0]), "=r"(r[1]), "=r"(r[2]), "=r"(r[3]) : "r"(addr));
}
__device__ __forceinline__ void ldm_x2(uint32_t* r, uint32_t addr) {
    asm volatile("ldmatrix.sync.aligned.m8n8.x2.shared.b16 {%0,%1}, [%2];"
                 : "=r"(r[0]), "=r"(r[1]) : "r"(addr));
}
__device__ __forceinline__ void mma_f16(float* d, const uint32_t* a, const uint32_t* b) {
    asm volatile(
        "mma.sync.aligned.m16n8k16.row.col.f32.f16.f16.f32 "
        "{%0,%1,%2,%3}, {%4,%5,%6,%7}, {%8,%9}, {%0,%1,%2,%3};"
        : "+f"(d[0]), "+f"(d[1]), "+f"(d[2]), "+f"(d[3])
        : "r"(a[0]), "r"(a[1]), "r"(a[2]), "r"(a[3]), "r"(b[0]), "r"(b[1]));
}

__global__ void __launch_bounds__(256, 2)
gemm_h_mma(const float* __restrict__ A,
           const __half* __restrict__ Whi,
           const __half* __restrict__ Wlo,
           const float* __restrict__ bvec,
           const float* __restrict__ root,
           const float* __restrict__ degs,
           __half* __restrict__ hout,
           float* __restrict__ out,
           int N)
{
    extern __shared__ __half smh[];

    const int tid  = threadIdx.x;
    const int wid  = tid >> 5;
    const int lane = tid & 31;
    const int g    = lane >> 2;
    const int tg   = lane & 3;
    const int m0   = blockIdx.x * 128;

    const int m_base = (wid & 1) * 64;
    const int n_base = (wid >> 1) * 32;

    // ---- copy pre-split W into padded smem (uint4 = 8 halves) ----
#pragma unroll
    for (int it = 0; it < 8; it++) {
        int idx = it * 256 + tid;
        int r = idx >> 4, c8 = (idx & 15) * 8;
        uint4 vh = *reinterpret_cast<const uint4*>(Whi + r * 128 + c8);
        uint4 vl = *reinterpret_cast<const uint4*>(Wlo + r * 128 + c8);
        *reinterpret_cast<uint4*>(smh + SWH + r * PITCH_W + c8) = vh;
        *reinterpret_cast<uint4*>(smh + SWL + r * PITCH_W + c8) = vl;
    }

    float acc[4][4][4];
#pragma unroll
    for (int mt = 0; mt < 4; mt++)
#pragma unroll
        for (int nt = 0; nt < 4; nt++)
#pragma unroll
            for (int q = 0; q < 4; q++) acc[mt][nt][q] = 0.f;

    const uint32_t sb = smem_u32(smh);
    const int aRow = lane & 15;
    const int aK   = (lane >> 4) * 8;
    const uint32_t aH0 = sb + (uint32_t)(SAH + (m_base + aRow) * PITCH_A + aK) * 2;
    const int bRow = lane & 7;
    const int bK   = ((lane >> 3) & 1) * 8;
    const uint32_t bH0 = sb + (uint32_t)(SWH + (n_base + bRow) * PITCH_W + bK) * 2;
    const uint32_t bL0 = sb + (uint32_t)(SWL + (n_base + bRow) * PITCH_W + bK) * 2;

    for (int kh = 0; kh < 2; kh++) {
        __syncthreads();
        // stage A K-half (128 x 64), fp16 hi only
#pragma unroll
        for (int it = 0; it < 8; it++) {
            int idx = it * 256 + tid;
            int r = idx >> 4, c4 = (idx & 15) * 4;
            int gm = m0 + r;
            float4 v = make_float4(0.f, 0.f, 0.f, 0.f);
            if (gm < N)
                v = *reinterpret_cast<const float4*>(A + (size_t)gm * NF + kh * 64 + c4);
            __half2 h01 = __floats2half2_rn(v.x, v.y);
            __half2 h23 = __floats2half2_rn(v.z, v.w);
            uint2 hs;
            hs.x = *reinterpret_cast<uint32_t*>(&h01);
            hs.y = *reinterpret_cast<uint32_t*>(&h23);
            *reinterpret_cast<uint2*>(smh + SAH + r * PITCH_A + c4) = hs;
        }
        __syncthreads();

#pragma unroll
        for (int ks = 0; ks < 4; ks++) {
            const uint32_t koA = (uint32_t)(ks * 16 * 2);
            const uint32_t koB = (uint32_t)((kh * 64 + ks * 16) * 2);
            uint32_t ah[4][4], bh[4][2], bl[4][2];
#pragma unroll
            for (int mt = 0; mt < 4; mt++)
                ldm_x4(ah[mt], aH0 + (uint32_t)(mt * 16 * PITCH_A * 2) + koA);
#pragma unroll
            for (int nt = 0; nt < 4; nt++) {
                ldm_x2(bh[nt], bH0 + (uint32_t)(nt * 8 * PITCH_W * 2) + koB);
                ldm_x2(bl[nt], bL0 + (uint32_t)(nt * 8 * PITCH_W * 2) + koB);
            }
#pragma unroll
            for (int mt = 0; mt < 4; mt++)
#pragma unroll
                for (int nt = 0; nt < 4; nt++) {
                    mma_f16(acc[mt][nt], ah[mt], bh[nt]);
                    mma_f16(acc[mt][nt], ah[mt], bl[nt]);
                }
        }
    }

    // ---- epilogue ----
#pragma unroll
    for (int nt = 0; nt < 4; nt++) {
        const int c = n_base + nt * 8 + 2 * tg;
        const float b0 = __ldg(bvec + c),  b1 = __ldg(bvec + c + 1);
        const float r0 = __ldg(root + c),  r1 = __ldg(root + c + 1);
#pragma unroll
        for (int mt = 0; mt < 4; mt++) {
            const int ra = m0 + m_base + mt * 16 + g;
            const int rb = ra + 8;
            if (ra < N) {
                float invd = 1.0f / __ldg(degs + ra);
                float h0 = acc[mt][nt][0] + b0;
                float h1 = acc[mt][nt][1] + b1;
                float2 ov = make_float2(fmaxf(h0 + r0, 0.f) * invd,
                                        fmaxf(h1 + r1, 0.f) * invd);
                __half2 hp = __floats2half2_rn(h0, h1);
                *reinterpret_cast<uint32_t*>(hout + (size_t)ra * NF + c) =
                    *reinterpret_cast<uint32_t*>(&hp);
                *reinterpret_cast<float2*>(out + (size_t)ra * NF + c) = ov;
            }
            if (rb < N) {
                float invd = 1.0f / __ldg(degs + rb);
                float h0 = acc[mt][nt][2] + b0;
                float h1 = acc[mt][nt][3] + b1;
                float2 ov = make_float2(fmaxf(h0 + r0, 0.f) * invd,
                                        fmaxf(h1 + r1, 0.f) * invd);
                __half2 hp = __floats2half2_rn(h0, h1);
                *reinterpret_cast<uint32_t*>(hout + (size_t)rb * NF + c) =
                    *reinterpret_cast<uint32_t*>(&hp);
                *reinterpret_cast<float2*>(out + (size_t)rb * NF + c) = ov;
            }
        }
    }
}

// ===========================================================================
// Kernel B (R13 design, best measured 158.4us): 8 edges/warp/iter,
// fp16 gathers, next-iter src prefetch, efeat in two 28-float chunks.
// ===========================================================================
__global__ void __launch_bounds__(256, 2)
edge_kernel(const float* __restrict__ efeat,   // [E,7]
            const float* __restrict__ norm,    // [E]
            const int*   __restrict__ src,
            const int*   __restrict__ dst,
            const float* __restrict__ We,      // [128,7]
            const float* __restrict__ be,      // [128]
            const __half* __restrict__ h,      // [N,128] fp16
            float* __restrict__ out,           // [N,128]
            int E)
{
    const int lane = threadIdx.x & 31;
    const int j0   = lane * 4;

    float w[4][EFD], bias[4];
#pragma unroll
    for (int j = 0; j < 4; j++) {
        bias[j] = __ldg(be + j0 + j);
#pragma unroll
        for (int k = 0; k < EFD; k++)
            w[j][k] = __ldg(We + (size_t)(j0 + j) * EFD + k);
    }

    const int warp_id = (blockIdx.x * blockDim.x + threadIdx.x) >> 5;
    const int nwarps  = (gridDim.x * blockDim.x) >> 5;
    const int Emain   = E & ~7;
    const int estep   = nwarps * 8;

    int e0 = warp_id * 8;
    int4 sa, sb;
    if (e0 < Emain) {
        sa = __ldcs(reinterpret_cast<const int4*>(src + e0));
        sb = __ldcs(reinterpret_cast<const int4*>(src + e0 + 4));
    }

    for (; e0 < Emain; e0 += estep) {
        const int s[8] = {sa.x, sa.y, sa.z, sa.w, sb.x, sb.y, sb.z, sb.w};
        uint2 hvr[8];
#pragma unroll
        for (int u = 0; u < 8; u++)
            hvr[u] = *reinterpret_cast<const uint2*>(h + (size_t)s[u] * NF + j0);

        const int e1 = e0 + estep;
        if (e1 < Emain) {
            sa = __ldcs(reinterpret_cast<const int4*>(src + e1));
            sb = __ldcs(reinterpret_cast<const int4*>(src + e1 + 4));
        }

        const int4   da = __ldcs(reinterpret_cast<const int4*>(dst + e0));
        const int4   db = __ldcs(reinterpret_cast<const int4*>(dst + e0 + 4));
        const float4 na = __ldcs(reinterpret_cast<const float4*>(norm + e0));
        const float4 nb = __ldcs(reinterpret_cast<const float4*>(norm + e0 + 4));

        const int   d[8]  = {da.x, da.y, da.z, da.w, db.x, db.y, db.z, db.w};
        const float nr[8] = {na.x, na.y, na.z, na.w, nb.x, nb.y, nb.z, nb.w};

#pragma unroll
        for (int cch = 0; cch < 2; cch++) {
            float ef[28];
#pragma unroll
            for (int q = 0; q < 7; q++)
                *reinterpret_cast<float4*>(&ef[q * 4]) =
                    __ldcs(reinterpret_cast<const float4*>(
                        efeat + (size_t)(e0 + cch * 4) * EFD + q * 4));

#pragma unroll
            for (int uu = 0; uu < 4; uu++) {
                const int u = cch * 4 + uu;
                float v0 = bias[0], v1 = bias[1], v2 = bias[2], v3 = bias[3];
#pragma unroll
                for (int k = 0; k < EFD; k++) {
                    float x = ef[uu * EFD + k];
                    v0 = fmaf(w[0][k], x, v0);
                    v1 = fmaf(w[1][k], x, v1);
                    v2 = fmaf(w[2][k], x, v2);
                    v3 = fmaf(w[3][k], x, v3);
                }
                __half2 p0 = *reinterpret_cast<__half2*>(&hvr[u].x);
                __half2 p1 = *reinterpret_cast<__half2*>(&hvr[u].y);
                float2 f01 = __half22float2(p0);
                float2 f23 = __half22float2(p1);

                v0 = fmaxf(f01.x + v0, 0.f) * nr[u];
                v1 = fmaxf(f01.y + v1, 0.f) * nr[u];
                v2 = fmaxf(f23.x + v2, 0.f) * nr[u];
                v3 = fmaxf(f23.y + v3, 0.f) * nr[u];

                float* p = out + (size_t)d[u] * NF + j0;
                asm volatile("red.global.add.v4.f32 [%0], {%1, %2, %3, %4};"
                             :: "l"(p), "f"(v0), "f"(v1), "f"(v2), "f"(v3)
                             : "memory");
            }
        }
    }

    // tail — warp 0
    if (warp_id == 0) {
        for (int e = Emain; e < E; e++) {
            const int   se = __ldg(src + e);
            const int   de = __ldg(dst + e);
            const float nre = __ldg(norm + e);
            float efs[EFD];
#pragma unroll
            for (int k = 0; k < EFD; k++)
                efs[k] = __ldg(efeat + (size_t)e * EFD + k);
            uint2 hraw = *reinterpret_cast<const uint2*>(h + (size_t)se * NF + j0);
            __half2 p0 = *reinterpret_cast<__half2*>(&hraw.x);
            __half2 p1 = *reinterpret_cast<__half2*>(&hraw.y);
            float2 f01 = __half22float2(p0);
            float2 f23 = __half22float2(p1);
            float v0 = bias[0], v1 = bias[1], v2 = bias[2], v3 = bias[3];
#pragma unroll
            for (int k = 0; k < EFD; k++) {
                v0 = fmaf(w[0][k], efs[k], v0);
                v1 = fmaf(w[1][k], efs[k], v1);
                v2 = fmaf(w[2][k], efs[k], v2);
                v3 = fmaf(w[3][k], efs[k], v3);
            }
            v0 = fmaxf(f01.x + v0, 0.f) * nre;
            v1 = fmaxf(f01.y + v1, 0.f) * nre;
            v2 = fmaxf(f23.x + v2, 0.f) * nre;
            v3 = fmaxf(f23.y + v3, 0.f) * nre;
            float* p = out + (size_t)de * NF + j0;
            asm volatile("red.global.add.v4.f32 [%0], {%1, %2, %3, %4};"
                         :: "l"(p), "f"(v0), "f"(v1), "f"(v2), "f"(v3)
                         : "memory");
        }
    }
}

// ---------------------------------------------------------------------------
// Launch.  Input order: nfeat, efeat, degs, norm, src, dst, W, b, We, be, root
// ---------------------------------------------------------------------------
extern "C" void kernel_launch(void* const* d_in, const int* in_sizes, int n_in,
                              void* d_out, int out_size)
{
    const float* nfeat = (const float*)d_in[0];
    const float* efeat = (const float*)d_in[1];
    const float* degs  = (const float*)d_in[2];
    const float* norm  = (const float*)d_in[3];
    const int*   src   = (const int*)  d_in[4];
    const int*   dst   = (const int*)  d_in[5];
    const float* W     = (const float*)d_in[6];
    const float* b     = (const float*)d_in[7];
    const float* We    = (const float*)d_in[8];
    const float* be    = (const float*)d_in[9];
    const float* root  = (const float*)d_in[10];
    float* out = (float*)d_out;

    const int N = in_sizes[0] / NF;
    const int E = in_sizes[4];

    __half *h, *whi, *wlo;
    cudaGetSymbolAddress((void**)&h,   g_h);
    cudaGetSymbolAddress((void**)&whi, g_Whi);
    cudaGetSymbolAddress((void**)&wlo, g_Wlo);

    cudaFuncSetAttribute(gemm_h_mma, cudaFuncAttributeMaxDynamicSharedMemorySize,
                         GEMM_SMEM_BYTES);

    split_w_kernel<<<16, 256>>>(W);

    int gridA = (N + 127) / 128;
    gemm_h_mma<<<gridA, 256, GEMM_SMEM_BYTES>>>(nfeat, whi, wlo, b, root, degs,
                                                h, out, N);

    int gridB = 1480;
    edge_kernel<<<gridB, 256>>>(efeat, norm, src, dst, We, be, h, out, E);
}